// round 16
// baseline (speedup 1.0000x reference)
#include <cuda_runtime.h>
#include <cuda_bf16.h>
#include <cstdint>

#define BATCH 16
#define SEQ 8192
#define DIM 256
#define NSPLIT 16
#define KCHUNK (SEQ / NSPLIT)   // 512

typedef __nv_bfloat16 bf16;

// ---------------- scratch (device globals: allocation-free) ----------------
__device__ float g_meansum[BATCH * DIM];
__device__ float g_part[(size_t)NSPLIT * BATCH * DIM * DIM];
__device__ float g_Pf[BATCH * DIM * DIM];
__device__ float g_trinv[BATCH];
__device__ float g_scale[BATCH];

__device__ bf16 g_xn_hi[(size_t)BATCH * SEQ * DIM];   // centered, [b][s][d]
__device__ bf16 g_xn_lo[(size_t)BATCH * SEQ * DIM];
__device__ bf16 g_P_hi[BATCH * DIM * DIM],  g_P_lo[BATCH * DIM * DIM];
__device__ bf16 g_T1_hi[BATCH * DIM * DIM], g_T1_lo[BATCH * DIM * DIM];
__device__ bf16 g_T2_hi[BATCH * DIM * DIM], g_T2_lo[BATCH * DIM * DIM];
__device__ bf16 g_Sn_hi[BATCH * DIM * DIM], g_Sn_lo[BATCH * DIM * DIM];

__device__ __forceinline__ const bf16* selh(int s) {
    switch (s) { case 0: return g_P_hi; case 1: return g_T1_hi;
                 case 2: return g_T2_hi; default: return g_Sn_hi; }
}
__device__ __forceinline__ const bf16* sell(int s) {
    switch (s) { case 0: return g_P_lo; case 1: return g_T1_lo;
                 case 2: return g_T2_lo; default: return g_Sn_lo; }
}
__device__ __forceinline__ bf16* selh_w(int s) {
    switch (s) { case 0: return g_P_hi; case 1: return g_T1_hi;
                 case 2: return g_T2_hi; default: return g_Sn_hi; }
}
__device__ __forceinline__ bf16* sell_w(int s) {
    switch (s) { case 0: return g_P_lo; case 1: return g_T1_lo;
                 case 2: return g_T2_lo; default: return g_Sn_lo; }
}

// ---------------- low-level helpers (base ISA only) ----------------
__device__ __forceinline__ uint32_t smem_u32(const void* p) {
    return (uint32_t)__cvta_generic_to_shared(p);
}
__device__ __forceinline__ void cp_async16(uint32_t dst, const void* src) {
    asm volatile("cp.async.cg.shared.global [%0], [%1], 16;\n" :: "r"(dst), "l"(src) : "memory");
}
#define CP_COMMIT() asm volatile("cp.async.commit_group;\n" ::: "memory")
#define CP_WAIT1()  asm volatile("cp.async.wait_group 1;\n" ::: "memory")
#define CP_WAIT0()  asm volatile("cp.async.wait_group 0;\n" ::: "memory")

__device__ __forceinline__ void ldx4(uint32_t (&r)[4], uint32_t addr) {
    asm volatile("ldmatrix.sync.aligned.m8n8.x4.shared.b16 {%0,%1,%2,%3}, [%4];\n"
                 : "=r"(r[0]), "=r"(r[1]), "=r"(r[2]), "=r"(r[3]) : "r"(addr));
}
__device__ __forceinline__ void ldx4t(uint32_t (&r)[4], uint32_t addr) {
    asm volatile("ldmatrix.sync.aligned.m8n8.x4.trans.shared.b16 {%0,%1,%2,%3}, [%4];\n"
                 : "=r"(r[0]), "=r"(r[1]), "=r"(r[2]), "=r"(r[3]) : "r"(addr));
}
__device__ __forceinline__ void mma_bf16(float (&c)[4], const uint32_t (&a)[4],
                                         uint32_t b0, uint32_t b1) {
    asm volatile(
        "mma.sync.aligned.m16n8k16.row.col.f32.bf16.bf16.f32 "
        "{%0,%1,%2,%3}, {%4,%5,%6,%7}, {%8,%9}, {%0,%1,%2,%3};\n"
        : "+f"(c[0]), "+f"(c[1]), "+f"(c[2]), "+f"(c[3])
        : "r"(a[0]), "r"(a[1]), "r"(a[2]), "r"(a[3]), "r"(b0), "r"(b1));
}
__device__ __forceinline__ void store_split2(bf16* dh, bf16* dl, size_t idx,
                                             float v0, float v1) {
    bf16 h0 = __float2bfloat16(v0);
    bf16 l0 = __float2bfloat16(v0 - __bfloat162float(h0));
    bf16 h1 = __float2bfloat16(v1);
    bf16 l1 = __float2bfloat16(v1 - __bfloat162float(h1));
    *reinterpret_cast<__nv_bfloat162*>(dh + idx) = __halves2bfloat162(h0, h1);
    *reinterpret_cast<__nv_bfloat162*>(dl + idx) = __halves2bfloat162(l0, l1);
}

// ---------------- tiled bf16-split GEMM core (BK=32, double buffered) ----------------
// A row-major [m][k], B [n][k].  Used by NS and out kernels (unchanged).
template <int BM, int BN, int WARPS_M, int WARPS_N>
struct Core {
    static constexpr int THREADS = WARPS_M * WARPS_N * 32;
    static constexpr int WTM = BM / WARPS_M;
    static constexpr int WTN = BN / WARPS_N;
    static constexpr int MT  = WTM / 16;
    static constexpr int NG  = WTN / 8;
    static constexpr int NLD = NG / 2;
    static constexpr int STRIDE_B = 80;
    static constexpr int TILE_A = BM * STRIDE_B;
    static constexpr int TILE_B = BN * STRIDE_B;
    static constexpr int STAGE  = 2 * TILE_A + 2 * TILE_B;

    __device__ static void load_stage(uint32_t sbase,
                                      const bf16* Ah, const bf16* Al, size_t lda,
                                      const bf16* Bh, const bf16* Bl, size_t ldb,
                                      int k0, int tid) {
        const int total = (2 * BM + 2 * BN) * 4;
        for (int i = tid; i < total; i += THREADS) {
            int r = i >> 2, seg = i & 3;
            const bf16* src; size_t ld; int row; uint32_t toff;
            if (r < BM)               { src = Ah; ld = lda; row = r;               toff = 0; }
            else if (r < 2 * BM)      { src = Al; ld = lda; row = r - BM;          toff = TILE_A; }
            else if (r < 2 * BM + BN) { src = Bh; ld = ldb; row = r - 2 * BM;      toff = 2 * TILE_A; }
            else                      { src = Bl; ld = ldb; row = r - 2 * BM - BN; toff = 2 * TILE_A + TILE_B; }
            uint32_t dst = sbase + toff + (uint32_t)row * STRIDE_B + seg * 16;
            cp_async16(dst, src + (size_t)row * ld + k0 + seg * 8);
        }
    }

    __device__ static void compute_stage(uint32_t sbase, int wm, int wn, int lane,
                                         float (&acc)[MT][NG][4]) {
        uint32_t sAh = sbase;
        uint32_t sAl = sbase + TILE_A;
        uint32_t sBh = sbase + 2 * TILE_A;
        uint32_t sBl = sbase + 2 * TILE_A + TILE_B;
        int aoff = (wm * WTM + (lane & 15)) * STRIDE_B + ((lane >> 4) * 8) * 2;
        int boff = (wn * WTN + (lane & 7) + ((lane >> 4) & 1) * 8) * STRIDE_B +
                   (((lane >> 3) & 1) * 8) * 2;
#pragma unroll
        for (int ks = 0; ks < 2; ks++) {
            int kb = ks * 32;
            uint32_t ah[MT][4], al[MT][4];
#pragma unroll
            for (int mt = 0; mt < MT; mt++) {
                ldx4(ah[mt], sAh + aoff + mt * 16 * STRIDE_B + kb);
                ldx4(al[mt], sAl + aoff + mt * 16 * STRIDE_B + kb);
            }
#pragma unroll
            for (int g = 0; g < NLD; g++) {
                uint32_t bh[4], bl[4];
                ldx4(bh, sBh + boff + g * 16 * STRIDE_B + kb);
                ldx4(bl, sBl + boff + g * 16 * STRIDE_B + kb);
#pragma unroll
                for (int mt = 0; mt < MT; mt++) {
                    mma_bf16(acc[mt][2 * g],     ah[mt], bh[0], bh[1]);
                    mma_bf16(acc[mt][2 * g + 1], ah[mt], bh[2], bh[3]);
                    mma_bf16(acc[mt][2 * g],     ah[mt], bl[0], bl[1]);
                    mma_bf16(acc[mt][2 * g + 1], ah[mt], bl[2], bl[3]);
                    mma_bf16(acc[mt][2 * g],     al[mt], bh[0], bh[1]);
                    mma_bf16(acc[mt][2 * g + 1], al[mt], bh[2], bh[3]);
                }
            }
        }
    }

    __device__ static void run(const bf16* Ah, const bf16* Al, size_t lda,
                               const bf16* Bh, const bf16* Bl, size_t ldb,
                               int K, char* smem, float (&acc)[MT][NG][4],
                               int tid, int wm, int wn, int lane) {
        uint32_t sb = smem_u32(smem);
        int nc = K / 32;
        load_stage(sb, Ah, Al, lda, Bh, Bl, ldb, 0, tid);
        CP_COMMIT();
        for (int c = 0; c < nc; c++) {
            uint32_t cur = sb + (uint32_t)(c & 1) * STAGE;
            if (c + 1 < nc) {
                load_stage(sb + (uint32_t)((c + 1) & 1) * STAGE,
                           Ah, Al, lda, Bh, Bl, ldb, (c + 1) * 32, tid);
                CP_COMMIT();
                CP_WAIT1();
            } else {
                CP_WAIT0();
            }
            __syncthreads();
            compute_stage(cur, wm, wn, lane, acc);
            __syncthreads();
        }
    }
};

using CoreA = Core<128, 128, 2, 2>;   // out: 4 warps, 64x64 warp tiles
using CoreB = Core<64, 128, 2, 4>;    // NS: 8 warps, 32x32 warp tiles

// ---------------- small kernels ----------------
__global__ void zero_mean_kernel() {
    int t = blockIdx.x * blockDim.x + threadIdx.x;
    if (t < BATCH * DIM) g_meansum[t] = 0.f;
}

__global__ void mean_kernel(const float* __restrict__ x) {
    int b = blockIdx.y;
    int d = threadIdx.x;
    int s0 = blockIdx.x * 128;
    const float* xp = x + ((size_t)b * SEQ + s0) * DIM + d;
    float sum = 0.f;
#pragma unroll 8
    for (int s = 0; s < 128; s++) sum += xp[(size_t)s * DIM];
    atomicAdd(&g_meansum[b * DIM + d], sum);
}

// xn = x - mu -> bf16 hi/lo, [s][d] layout ONLY
// grid (SEQ/32, BATCH), 256 threads (thread = d); fully coalesced both directions
__global__ void convert_kernel(const float* __restrict__ x) {
    int b = blockIdx.y;
    int s0 = blockIdx.x * 32;
    int d = threadIdx.x;

    float mu = g_meansum[b * DIM + d] * (1.f / SEQ);
    const float* xp = x + ((size_t)b * SEQ + s0) * DIM + d;
    bf16* nh = g_xn_hi + ((size_t)b * SEQ + s0) * DIM + d;
    bf16* nl = g_xn_lo + ((size_t)b * SEQ + s0) * DIM + d;

#pragma unroll
    for (int r = 0; r < 32; r++) {
        float v = xp[(size_t)r * DIM] - mu;
        bf16 h = __float2bfloat16(v);
        bf16 l = __float2bfloat16(v - __bfloat162float(h));
        nh[(size_t)r * DIM] = h;
        nl[(size_t)r * DIM] = l;
    }
}

// ---------------- sigma: xn^T xn directly from [s][d] via ldmatrix.trans ----------------
// grid (3, NSPLIT, BATCH), 128 threads; dyn smem 2 * SG_STAGE
#define SG_STRIDE 272                   // 256B data + 16B pad (conflict-free ldmatrix)
#define SG_TILE   (32 * SG_STRIDE)      // 8704
#define SG_STAGE  (4 * SG_TILE)         // 34816
__global__ void __launch_bounds__(128) sigma_mma_kernel() {
    extern __shared__ char smem[];
    uint32_t sb = smem_u32(smem);
    int tid = threadIdx.x, lane = tid & 31, wid = tid >> 5;
    int wm = wid & 1, wn = wid >> 1;
    int tile = blockIdx.x;                    // 0:(0,0) 1:(1,1) 2:(1,0)
    int tm = (tile == 0) ? 0 : 1;
    int tn = (tile == 1) ? 1 : 0;
    bool diag = (tile != 2);
    int split = blockIdx.y, b = blockIdx.z;

    size_t rowbase = ((size_t)b * SEQ + (size_t)split * KCHUNK) * DIM;
    const bf16* mats[4];
    mats[0] = g_xn_hi + rowbase + tm * 128;   // A hi: rows s, 128-d slice
    mats[1] = g_xn_lo + rowbase + tm * 128;
    mats[2] = g_xn_hi + rowbase + tn * 128;
    mats[3] = g_xn_lo + rowbase + tn * 128;
    const int nmat = diag ? 2 : 4;

    float acc[4][8][4] = {};

    // fragment addressing (trans-ldmatrix layout == movmatrix layout from R15)
    int arow = (lane & 7) + ((lane >> 4) & 1) * 8;
    int acol = (wm * 64 + ((lane >> 3) & 1) * 8) * 2;
    int brow = (lane & 7) + ((lane >> 3) & 1) * 8;
    int bcol = (wn * 64 + ((lane >> 4) & 1) * 8) * 2;

    // prologue
    for (int i = tid; i < nmat * 512; i += 128) {
        int mat = i >> 9, r = (i >> 4) & 31, seg = i & 15;
        cp_async16(sb + mat * SG_TILE + (uint32_t)r * SG_STRIDE + seg * 16,
                   mats[mat] + (size_t)r * DIM + seg * 8);
    }
    CP_COMMIT();

    for (int c = 0; c < KCHUNK / 32; c++) {
        if (c + 1 < KCHUNK / 32) {
            uint32_t nb = (uint32_t)((c + 1) & 1) * SG_STAGE;
            int s0 = (c + 1) * 32;
            for (int i = tid; i < nmat * 512; i += 128) {
                int mat = i >> 9, r = (i >> 4) & 31, seg = i & 15;
                cp_async16(sb + nb + mat * SG_TILE + (uint32_t)r * SG_STRIDE + seg * 16,
                           mats[mat] + (size_t)(s0 + r) * DIM + seg * 8);
            }
            CP_COMMIT();
            CP_WAIT1();
        } else {
            CP_WAIT0();
        }
        __syncthreads();

        uint32_t base = sb + (uint32_t)(c & 1) * SG_STAGE;
        uint32_t sAh = base, sAl = base + SG_TILE;
        uint32_t sBh = diag ? sAh : base + 2 * SG_TILE;
        uint32_t sBl = diag ? sAl : base + 3 * SG_TILE;
#pragma unroll
        for (int ks = 0; ks < 2; ks++) {
            uint32_t ah[4][4], al[4][4];
#pragma unroll
            for (int mt = 0; mt < 4; mt++) {
                ldx4t(ah[mt], sAh + (uint32_t)(ks * 16 + arow) * SG_STRIDE + acol + mt * 32);
                ldx4t(al[mt], sAl + (uint32_t)(ks * 16 + arow) * SG_STRIDE + acol + mt * 32);
            }
#pragma unroll
            for (int g = 0; g < 4; g++) {
                uint32_t bh[4], bl[4];
                ldx4t(bh, sBh + (uint32_t)(ks * 16 + brow) * SG_STRIDE + bcol + g * 32);
                ldx4t(bl, sBl + (uint32_t)(ks * 16 + brow) * SG_STRIDE + bcol + g * 32);
#pragma unroll
                for (int mt = 0; mt < 4; mt++) {
                    mma_bf16(acc[mt][2 * g],     ah[mt], bh[0], bh[1]);
                    mma_bf16(acc[mt][2 * g + 1], ah[mt], bh[2], bh[3]);
                    mma_bf16(acc[mt][2 * g],     ah[mt], bl[0], bl[1]);
                    mma_bf16(acc[mt][2 * g + 1], ah[mt], bl[2], bl[3]);
                    mma_bf16(acc[mt][2 * g],     al[mt], bh[0], bh[1]);
                    mma_bf16(acc[mt][2 * g + 1], al[mt], bh[2], bh[3]);
                }
            }
        }
        __syncthreads();
    }

    float* dst = g_part + (size_t)(split * BATCH + b) * DIM * DIM;
#pragma unroll
    for (int mt = 0; mt < 4; mt++) {
        int row = tm * 128 + wm * 64 + mt * 16 + (lane >> 2);
#pragma unroll
        for (int g = 0; g < 8; g++) {
            int col = tn * 128 + wn * 64 + g * 8 + (lane & 3) * 2;
            *reinterpret_cast<float2*>(&dst[(size_t)row * DIM + col]) =
                make_float2(acc[mt][g][0], acc[mt][g][1]);
            *reinterpret_cast<float2*>(&dst[(size_t)(row + 8) * DIM + col]) =
                make_float2(acc[mt][g][2], acc[mt][g][3]);
        }
    }
}

// ---------------- trace + scales ----------------
__global__ void trace_kernel() {
    __shared__ float red[256];
    int b = blockIdx.x, d = threadIdx.x;
    float v = 0.f;
#pragma unroll
    for (int s = 0; s < NSPLIT; s++)
        v += g_part[(size_t)(s * BATCH + b) * DIM * DIM + d * (DIM + 1)];
    red[d] = v;
    __syncthreads();
    for (int off = 128; off > 0; off >>= 1) {
        if (d < off) red[d] += red[d + off];
        __syncthreads();
    }
    if (d == 0) {
        float tr = red[0];
        g_trinv[b] = 1.f / tr;
        g_scale[b] = rsqrtf(tr / (float)(SEQ - 1));
    }
}

// ---------------- Sn build (+ P init fused) ----------------
// grid (256, BATCH), 256 threads
__global__ void sn_kernel() {
    int i = blockIdx.x, b = blockIdx.y, j = threadIdx.x;
    int src = (i < 128 && j >= 128) ? j * DIM + i : i * DIM + j;
    float v = 0.f;
#pragma unroll
    for (int s = 0; s < NSPLIT; s++)
        v += g_part[(size_t)(s * BATCH + b) * DIM * DIM + src];
    v *= g_trinv[b];
    size_t idx = (size_t)b * DIM * DIM + i * DIM + j;
    bf16 h = __float2bfloat16(v);
    g_Sn_hi[idx] = h;
    g_Sn_lo[idx] = __float2bfloat16(v - __bfloat162float(h));
    float pv = (i == j) ? 1.f : 0.f;
    g_Pf[idx] = pv;
    g_P_hi[idx] = __float2bfloat16(pv);
    g_P_lo[idx] = __float2bfloat16(0.f);
}

// ---------------- NS gemm body ----------------
__device__ __forceinline__ void ns_gemm_body(int aSel, int bSel, int dSel, int mode,
                                             int tm, int tn, int b, char* smem) {
    int tid = threadIdx.x, lane = tid & 31, wid = tid >> 5;
    int wm = wid & 1, wn = wid >> 1;
    size_t mb = (size_t)b * DIM * DIM;

    const bf16* Ah = selh(aSel) + mb + (size_t)tm * 64 * DIM;
    const bf16* Al = sell(aSel) + mb + (size_t)tm * 64 * DIM;
    const bf16* Bh = selh(bSel) + mb + (size_t)tn * 128 * DIM;
    const bf16* Bl = sell(bSel) + mb + (size_t)tn * 128 * DIM;

    float acc[CoreB::MT][CoreB::NG][4] = {};
    CoreB::run(Ah, Al, DIM, Bh, Bl, DIM, DIM, smem, acc, tid, wm, wn, lane);

    bf16* dh = selh_w(dSel) + mb;
    bf16* dl = sell_w(dSel) + mb;
    float* pf = g_Pf + mb;
#pragma unroll
    for (int mt = 0; mt < CoreB::MT; mt++) {
        int row = tm * 64 + wm * CoreB::WTM + mt * 16 + (lane >> 2);
#pragma unroll
        for (int g = 0; g < CoreB::NG; g++) {
            int col = tn * 128 + wn * CoreB::WTN + g * 8 + (lane & 3) * 2;
#pragma unroll
            for (int h = 0; h < 2; h++) {
                size_t idx = (size_t)(row + h * 8) * DIM + col;
                float v0 = acc[mt][g][2 * h], v1 = acc[mt][g][2 * h + 1];
                if (mode == 2) {
                    v0 = 1.5f * pf[idx] - 0.5f * v0;
                    v1 = 1.5f * pf[idx + 1] - 0.5f * v1;
                    pf[idx] = v0;
                    pf[idx + 1] = v1;
                }
                store_split2(dh, dl, idx, v0, v1);
            }
        }
    }
}

// pair launch: blockIdx.x 0..15 -> sub 0: T1 = P@P ; sub 1: T2 = P@Sn
// grid (16, BATCH), 256 threads
__global__ void __launch_bounds__(256) ns_pair_kernel() {
    extern __shared__ char smem[];
    int sub = blockIdx.x >> 3;
    int t = blockIdx.x & 7;
    int tm = t & 3, tn = t >> 2;
    if (sub == 0) ns_gemm_body(0, 0, 1, 0, tm, tn, blockIdx.y, smem);
    else          ns_gemm_body(0, 3, 2, 0, tm, tn, blockIdx.y, smem);
}

// final: P = 1.5P - 0.5*T1@T2^T
// grid (8, BATCH), 256 threads
__global__ void __launch_bounds__(256) ns_fin_kernel() {
    extern __shared__ char smem[];
    int tm = blockIdx.x & 3, tn = blockIdx.x >> 2;
    ns_gemm_body(1, 2, 0, 2, tm, tn, blockIdx.y, smem);
}

// ---------------- out = (xn @ P) * scale ----------------
// grid (2, SEQ/128, BATCH), 128 threads
__global__ void __launch_bounds__(128) out_mma_kernel(float* __restrict__ out) {
    extern __shared__ char smem[];
    int tid = threadIdx.x, lane = tid & 31, wid = tid >> 5;
    int wm = wid & 1, wn = wid >> 1;
    int tn = blockIdx.x;
    int s0 = blockIdx.y * 128;
    int b = blockIdx.z;

    const bf16* Ah = g_xn_hi + ((size_t)b * SEQ + s0) * DIM;
    const bf16* Al = g_xn_lo + ((size_t)b * SEQ + s0) * DIM;
    const bf16* Bh = g_P_hi + (size_t)b * DIM * DIM + (size_t)tn * 128 * DIM;
    const bf16* Bl = g_P_lo + (size_t)b * DIM * DIM + (size_t)tn * 128 * DIM;

    float acc[CoreA::MT][CoreA::NG][4] = {};
    CoreA::run(Ah, Al, DIM, Bh, Bl, DIM, DIM, smem, acc, tid, wm, wn, lane);

    float sc = g_scale[b];
    float* ob = out + ((size_t)b * SEQ + s0) * DIM + tn * 128;
#pragma unroll
    for (int mt = 0; mt < CoreA::MT; mt++) {
        int row = wm * CoreA::WTM + mt * 16 + (lane >> 2);
#pragma unroll
        for (int g = 0; g < CoreA::NG; g++) {
            int col = wn * CoreA::WTN + g * 8 + (lane & 3) * 2;
            *reinterpret_cast<float2*>(&ob[(size_t)row * DIM + col]) =
                make_float2(acc[mt][g][0] * sc, acc[mt][g][1] * sc);
            *reinterpret_cast<float2*>(&ob[(size_t)(row + 8) * DIM + col]) =
                make_float2(acc[mt][g][2] * sc, acc[mt][g][3] * sc);
        }
    }
}

// ---------------- launch ----------------
extern "C" void kernel_launch(void* const* d_in, const int* in_sizes, int n_in,
                              void* d_out, int out_size) {
    const float* x = (const float*)d_in[0];
    float* out = (float*)d_out;

    static bool attrs_set = false;
    if (!attrs_set) {
        cudaFuncSetAttribute(sigma_mma_kernel, cudaFuncAttributeMaxDynamicSharedMemorySize, 2 * SG_STAGE);
        cudaFuncSetAttribute(out_mma_kernel, cudaFuncAttributeMaxDynamicSharedMemorySize, 2 * CoreA::STAGE);
        cudaFuncSetAttribute(ns_pair_kernel, cudaFuncAttributeMaxDynamicSharedMemorySize, 2 * CoreB::STAGE);
        cudaFuncSetAttribute(ns_fin_kernel, cudaFuncAttributeMaxDynamicSharedMemorySize, 2 * CoreB::STAGE);
        attrs_set = true;
    }

    zero_mean_kernel<<<16, 256>>>();
    mean_kernel<<<dim3(SEQ / 128, BATCH), 256>>>(x);
    convert_kernel<<<dim3(SEQ / 32, BATCH), 256>>>(x);
    sigma_mma_kernel<<<dim3(3, NSPLIT, BATCH), 128, 2 * SG_STAGE>>>();
    trace_kernel<<<BATCH, 256>>>();
    sn_kernel<<<dim3(256, BATCH), 256>>>();

    for (int it = 0; it < 4; it++) {
        ns_pair_kernel<<<dim3(16, BATCH), 256, 2 * CoreB::STAGE>>>();  // T1=P@P, T2=P@Sn
        ns_fin_kernel<<<dim3(8, BATCH), 256, 2 * CoreB::STAGE>>>();    // P=1.5P-0.5*T1@T2^T
    }

    out_mma_kernel<<<dim3(2, SEQ / 128, BATCH), 128, 2 * CoreA::STAGE>>>(out);
}

// round 17
// speedup vs baseline: 1.4508x; 1.4508x over previous
#include <cuda_runtime.h>
#include <cuda_bf16.h>
#include <cstdint>

#define BATCH 16
#define SEQ 8192
#define DIM 256
#define NSPLIT 16
#define KCHUNK (SEQ / NSPLIT)   // 512

typedef __nv_bfloat16 bf16;

// ---------------- scratch (device globals: allocation-free) ----------------
__device__ float g_meansum[BATCH * DIM];
__device__ float g_part[(size_t)NSPLIT * BATCH * DIM * DIM];
__device__ float g_Pf[BATCH * DIM * DIM];
__device__ float g_trinv[BATCH];
__device__ float g_scale[BATCH];

__device__ bf16 g_xn_hi[(size_t)BATCH * SEQ * DIM];   // centered, [b][s][d]
__device__ bf16 g_xn_lo[(size_t)BATCH * SEQ * DIM];
__device__ bf16 g_P_hi[BATCH * DIM * DIM],  g_P_lo[BATCH * DIM * DIM];
__device__ bf16 g_T1_hi[BATCH * DIM * DIM], g_T1_lo[BATCH * DIM * DIM];
__device__ bf16 g_T2_hi[BATCH * DIM * DIM], g_T2_lo[BATCH * DIM * DIM];
__device__ bf16 g_Sn_hi[BATCH * DIM * DIM], g_Sn_lo[BATCH * DIM * DIM];

__device__ __forceinline__ const bf16* selh(int s) {
    switch (s) { case 0: return g_P_hi; case 1: return g_T1_hi;
                 case 2: return g_T2_hi; default: return g_Sn_hi; }
}
__device__ __forceinline__ const bf16* sell(int s) {
    switch (s) { case 0: return g_P_lo; case 1: return g_T1_lo;
                 case 2: return g_T2_lo; default: return g_Sn_lo; }
}
__device__ __forceinline__ bf16* selh_w(int s) {
    switch (s) { case 0: return g_P_hi; case 1: return g_T1_hi;
                 case 2: return g_T2_hi; default: return g_Sn_hi; }
}
__device__ __forceinline__ bf16* sell_w(int s) {
    switch (s) { case 0: return g_P_lo; case 1: return g_T1_lo;
                 case 2: return g_T2_lo; default: return g_Sn_lo; }
}

// ---------------- low-level helpers (base ISA only) ----------------
__device__ __forceinline__ uint32_t smem_u32(const void* p) {
    return (uint32_t)__cvta_generic_to_shared(p);
}
__device__ __forceinline__ void cp_async16(uint32_t dst, const void* src) {
    asm volatile("cp.async.cg.shared.global [%0], [%1], 16;\n" :: "r"(dst), "l"(src) : "memory");
}
#define CP_COMMIT() asm volatile("cp.async.commit_group;\n" ::: "memory")
#define CP_WAIT1()  asm volatile("cp.async.wait_group 1;\n" ::: "memory")
#define CP_WAIT0()  asm volatile("cp.async.wait_group 0;\n" ::: "memory")

__device__ __forceinline__ void ldx4(uint32_t (&r)[4], uint32_t addr) {
    asm volatile("ldmatrix.sync.aligned.m8n8.x4.shared.b16 {%0,%1,%2,%3}, [%4];\n"
                 : "=r"(r[0]), "=r"(r[1]), "=r"(r[2]), "=r"(r[3]) : "r"(addr));
}
__device__ __forceinline__ uint32_t movm(uint32_t v) {
    uint32_t r;
    asm volatile("movmatrix.sync.aligned.m8n8.trans.b16 %0, %1;\n" : "=r"(r) : "r"(v));
    return r;
}
__device__ __forceinline__ void mma_bf16(float (&c)[4], const uint32_t (&a)[4],
                                         uint32_t b0, uint32_t b1) {
    asm volatile(
        "mma.sync.aligned.m16n8k16.row.col.f32.bf16.bf16.f32 "
        "{%0,%1,%2,%3}, {%4,%5,%6,%7}, {%8,%9}, {%0,%1,%2,%3};\n"
        : "+f"(c[0]), "+f"(c[1]), "+f"(c[2]), "+f"(c[3])
        : "r"(a[0]), "r"(a[1]), "r"(a[2]), "r"(a[3]), "r"(b0), "r"(b1));
}
__device__ __forceinline__ void store_split2(bf16* dh, bf16* dl, size_t idx,
                                             float v0, float v1) {
    bf16 h0 = __float2bfloat16(v0);
    bf16 l0 = __float2bfloat16(v0 - __bfloat162float(h0));
    bf16 h1 = __float2bfloat16(v1);
    bf16 l1 = __float2bfloat16(v1 - __bfloat162float(h1));
    *reinterpret_cast<__nv_bfloat162*>(dh + idx) = __halves2bfloat162(h0, h1);
    *reinterpret_cast<__nv_bfloat162*>(dl + idx) = __halves2bfloat162(l0, l1);
}

// ---------------- tiled bf16-split GEMM core (BK=32, double buffered) ----------------
// A row-major [m][k], B [n][k].  Used by NS and out kernels.
template <int BM, int BN, int WARPS_M, int WARPS_N>
struct Core {
    static constexpr int THREADS = WARPS_M * WARPS_N * 32;
    static constexpr int WTM = BM / WARPS_M;
    static constexpr int WTN = BN / WARPS_N;
    static constexpr int MT  = WTM / 16;
    static constexpr int NG  = WTN / 8;
    static constexpr int NLD = NG / 2;
    static constexpr int STRIDE_B = 80;
    static constexpr int TILE_A = BM * STRIDE_B;
    static constexpr int TILE_B = BN * STRIDE_B;
    static constexpr int STAGE  = 2 * TILE_A + 2 * TILE_B;

    __device__ static void load_stage(uint32_t sbase,
                                      const bf16* Ah, const bf16* Al, size_t lda,
                                      const bf16* Bh, const bf16* Bl, size_t ldb,
                                      int k0, int tid) {
        const int total = (2 * BM + 2 * BN) * 4;
        for (int i = tid; i < total; i += THREADS) {
            int r = i >> 2, seg = i & 3;
            const bf16* src; size_t ld; int row; uint32_t toff;
            if (r < BM)               { src = Ah; ld = lda; row = r;               toff = 0; }
            else if (r < 2 * BM)      { src = Al; ld = lda; row = r - BM;          toff = TILE_A; }
            else if (r < 2 * BM + BN) { src = Bh; ld = ldb; row = r - 2 * BM;      toff = 2 * TILE_A; }
            else                      { src = Bl; ld = ldb; row = r - 2 * BM - BN; toff = 2 * TILE_A + TILE_B; }
            uint32_t dst = sbase + toff + (uint32_t)row * STRIDE_B + seg * 16;
            cp_async16(dst, src + (size_t)row * ld + k0 + seg * 8);
        }
    }

    __device__ static void compute_stage(uint32_t sbase, int wm, int wn, int lane,
                                         float (&acc)[MT][NG][4]) {
        uint32_t sAh = sbase;
        uint32_t sAl = sbase + TILE_A;
        uint32_t sBh = sbase + 2 * TILE_A;
        uint32_t sBl = sbase + 2 * TILE_A + TILE_B;
        int aoff = (wm * WTM + (lane & 15)) * STRIDE_B + ((lane >> 4) * 8) * 2;
        int boff = (wn * WTN + (lane & 7) + ((lane >> 4) & 1) * 8) * STRIDE_B +
                   (((lane >> 3) & 1) * 8) * 2;
#pragma unroll
        for (int ks = 0; ks < 2; ks++) {
            int kb = ks * 32;
            uint32_t ah[MT][4], al[MT][4];
#pragma unroll
            for (int mt = 0; mt < MT; mt++) {
                ldx4(ah[mt], sAh + aoff + mt * 16 * STRIDE_B + kb);
                ldx4(al[mt], sAl + aoff + mt * 16 * STRIDE_B + kb);
            }
#pragma unroll
            for (int g = 0; g < NLD; g++) {
                uint32_t bh[4], bl[4];
                ldx4(bh, sBh + boff + g * 16 * STRIDE_B + kb);
                ldx4(bl, sBl + boff + g * 16 * STRIDE_B + kb);
#pragma unroll
                for (int mt = 0; mt < MT; mt++) {
                    mma_bf16(acc[mt][2 * g],     ah[mt], bh[0], bh[1]);
                    mma_bf16(acc[mt][2 * g + 1], ah[mt], bh[2], bh[3]);
                    mma_bf16(acc[mt][2 * g],     ah[mt], bl[0], bl[1]);
                    mma_bf16(acc[mt][2 * g + 1], ah[mt], bl[2], bl[3]);
                    mma_bf16(acc[mt][2 * g],     al[mt], bh[0], bh[1]);
                    mma_bf16(acc[mt][2 * g + 1], al[mt], bh[2], bh[3]);
                }
            }
        }
    }

    __device__ static void run(const bf16* Ah, const bf16* Al, size_t lda,
                               const bf16* Bh, const bf16* Bl, size_t ldb,
                               int K, char* smem, float (&acc)[MT][NG][4],
                               int tid, int wm, int wn, int lane) {
        uint32_t sb = smem_u32(smem);
        int nc = K / 32;
        load_stage(sb, Ah, Al, lda, Bh, Bl, ldb, 0, tid);
        CP_COMMIT();
        for (int c = 0; c < nc; c++) {
            uint32_t cur = sb + (uint32_t)(c & 1) * STAGE;
            if (c + 1 < nc) {
                load_stage(sb + (uint32_t)((c + 1) & 1) * STAGE,
                           Ah, Al, lda, Bh, Bl, ldb, (c + 1) * 32, tid);
                CP_COMMIT();
                CP_WAIT1();
            } else {
                CP_WAIT0();
            }
            __syncthreads();
            compute_stage(cur, wm, wn, lane, acc);
            __syncthreads();
        }
    }
};

using CoreA = Core<128, 128, 2, 2>;   // out: 4 warps, 64x64 warp tiles
using CoreB = Core<64, 128, 2, 4>;    // NS: 8 warps, 32x32 warp tiles

// ---------------- small kernels ----------------
__global__ void zero_mean_kernel() {
    int t = blockIdx.x * blockDim.x + threadIdx.x;
    if (t < BATCH * DIM) g_meansum[t] = 0.f;
}

__global__ void mean_kernel(const float* __restrict__ x) {
    int b = blockIdx.y;
    int d = threadIdx.x;
    int s0 = blockIdx.x * 128;
    const float* xp = x + ((size_t)b * SEQ + s0) * DIM + d;
    float sum = 0.f;
#pragma unroll 8
    for (int s = 0; s < 128; s++) sum += xp[(size_t)s * DIM];
    atomicAdd(&g_meansum[b * DIM + d], sum);
}

// xn = x - mu -> bf16 hi/lo, [s][d] layout ONLY (xt eliminated)
// grid (SEQ/32, BATCH), 256 threads (thread = d); fully coalesced both directions
__global__ void convert_kernel(const float* __restrict__ x) {
    int b = blockIdx.y;
    int s0 = blockIdx.x * 32;
    int d = threadIdx.x;

    float mu = g_meansum[b * DIM + d] * (1.f / SEQ);
    const float* xp = x + ((size_t)b * SEQ + s0) * DIM + d;
    bf16* nh = g_xn_hi + ((size_t)b * SEQ + s0) * DIM + d;
    bf16* nl = g_xn_lo + ((size_t)b * SEQ + s0) * DIM + d;

#pragma unroll
    for (int r = 0; r < 32; r++) {
        float v = xp[(size_t)r * DIM] - mu;
        bf16 h = __float2bfloat16(v);
        bf16 l = __float2bfloat16(v - __bfloat162float(h));
        nh[(size_t)r * DIM] = h;
        nl[(size_t)r * DIM] = l;
    }
}

// ---------------- sigma: xn^T xn directly from [s][d] via movmatrix ----------------
// grid (3, NSPLIT, BATCH), 128 threads; dyn smem 2 * SG_STAGE
#define SG_STRIDE 272                   // 256B data + 16B pad (conflict-free ldmatrix)
#define SG_TILE   (32 * SG_STRIDE)      // 8704
#define SG_STAGE  (4 * SG_TILE)         // 34816
__global__ void __launch_bounds__(128) sigma_mma_kernel() {
    extern __shared__ char smem[];
    uint32_t sb = smem_u32(smem);
    int tid = threadIdx.x, lane = tid & 31, wid = tid >> 5;
    int wm = wid & 1, wn = wid >> 1;
    int tile = blockIdx.x;                    // 0:(0,0) 1:(1,1) 2:(1,0)
    int tm = (tile == 0) ? 0 : 1;
    int tn = (tile == 1) ? 1 : 0;
    bool diag = (tile != 2);
    int split = blockIdx.y, b = blockIdx.z;

    size_t rowbase = ((size_t)b * SEQ + (size_t)split * KCHUNK) * DIM;
    const bf16* mats[4];
    mats[0] = g_xn_hi + rowbase + tm * 128;   // A hi: rows s, 128-d slice
    mats[1] = g_xn_lo + rowbase + tm * 128;
    mats[2] = g_xn_hi + rowbase + tn * 128;
    mats[3] = g_xn_lo + rowbase + tn * 128;
    const int nmat = diag ? 2 : 4;

    float acc[4][8][4] = {};

    // fragment addressing (movmatrix layout):
    int arow = (lane & 7) + ((lane >> 4) & 1) * 8;
    int acol = (wm * 64 + ((lane >> 3) & 1) * 8) * 2;
    int brow = (lane & 7) + ((lane >> 3) & 1) * 8;
    int bcol = (wn * 64 + ((lane >> 4) & 1) * 8) * 2;

    // prologue
    for (int i = tid; i < nmat * 512; i += 128) {
        int mat = i >> 9, r = (i >> 4) & 31, seg = i & 15;
        cp_async16(sb + mat * SG_TILE + (uint32_t)r * SG_STRIDE + seg * 16,
                   mats[mat] + (size_t)r * DIM + seg * 8);
    }
    CP_COMMIT();

    for (int c = 0; c < KCHUNK / 32; c++) {
        if (c + 1 < KCHUNK / 32) {
            uint32_t nb = (uint32_t)((c + 1) & 1) * SG_STAGE;
            int s0 = (c + 1) * 32;
            for (int i = tid; i < nmat * 512; i += 128) {
                int mat = i >> 9, r = (i >> 4) & 31, seg = i & 15;
                cp_async16(sb + nb + mat * SG_TILE + (uint32_t)r * SG_STRIDE + seg * 16,
                           mats[mat] + (size_t)(s0 + r) * DIM + seg * 8);
            }
            CP_COMMIT();
            CP_WAIT1();
        } else {
            CP_WAIT0();
        }
        __syncthreads();

        uint32_t base = sb + (uint32_t)(c & 1) * SG_STAGE;
        uint32_t sAh = base, sAl = base + SG_TILE;
        uint32_t sBh = diag ? sAh : base + 2 * SG_TILE;
        uint32_t sBl = diag ? sAl : base + 3 * SG_TILE;
#pragma unroll
        for (int ks = 0; ks < 2; ks++) {
            uint32_t ah[4][4], al[4][4];
#pragma unroll
            for (int mt = 0; mt < 4; mt++) {
                ldx4(ah[mt], sAh + (uint32_t)(ks * 16 + arow) * SG_STRIDE + acol + mt * 32);
                ldx4(al[mt], sAl + (uint32_t)(ks * 16 + arow) * SG_STRIDE + acol + mt * 32);
#pragma unroll
                for (int i = 0; i < 4; i++) {
                    ah[mt][i] = movm(ah[mt][i]);
                    al[mt][i] = movm(al[mt][i]);
                }
            }
#pragma unroll
            for (int g = 0; g < 4; g++) {
                uint32_t bh[4], bl[4];
                ldx4(bh, sBh + (uint32_t)(ks * 16 + brow) * SG_STRIDE + bcol + g * 32);
                ldx4(bl, sBl + (uint32_t)(ks * 16 + brow) * SG_STRIDE + bcol + g * 32);
#pragma unroll
                for (int i = 0; i < 4; i++) {
                    bh[i] = movm(bh[i]);
                    bl[i] = movm(bl[i]);
                }
#pragma unroll
                for (int mt = 0; mt < 4; mt++) {
                    mma_bf16(acc[mt][2 * g],     ah[mt], bh[0], bh[1]);
                    mma_bf16(acc[mt][2 * g + 1], ah[mt], bh[2], bh[3]);
                    mma_bf16(acc[mt][2 * g],     ah[mt], bl[0], bl[1]);
                    mma_bf16(acc[mt][2 * g + 1], ah[mt], bl[2], bl[3]);
                    mma_bf16(acc[mt][2 * g],     al[mt], bh[0], bh[1]);
                    mma_bf16(acc[mt][2 * g + 1], al[mt], bh[2], bh[3]);
                }
            }
        }
        __syncthreads();
    }

    float* dst = g_part + (size_t)(split * BATCH + b) * DIM * DIM;
#pragma unroll
    for (int mt = 0; mt < 4; mt++) {
        int row = tm * 128 + wm * 64 + mt * 16 + (lane >> 2);
#pragma unroll
        for (int g = 0; g < 8; g++) {
            int col = tn * 128 + wn * 64 + g * 8 + (lane & 3) * 2;
            *reinterpret_cast<float2*>(&dst[(size_t)row * DIM + col]) =
                make_float2(acc[mt][g][0], acc[mt][g][1]);
            *reinterpret_cast<float2*>(&dst[(size_t)(row + 8) * DIM + col]) =
                make_float2(acc[mt][g][2], acc[mt][g][3]);
        }
    }
}

// ---------------- trace + scales ----------------
__global__ void trace_kernel() {
    __shared__ float red[256];
    int b = blockIdx.x, d = threadIdx.x;
    float v = 0.f;
#pragma unroll
    for (int s = 0; s < NSPLIT; s++)
        v += g_part[(size_t)(s * BATCH + b) * DIM * DIM + d * (DIM + 1)];
    red[d] = v;
    __syncthreads();
    for (int off = 128; off > 0; off >>= 1) {
        if (d < off) red[d] += red[d + off];
        __syncthreads();
    }
    if (d == 0) {
        float tr = red[0];
        g_trinv[b] = 1.f / tr;
        g_scale[b] = rsqrtf(tr / (float)(SEQ - 1));
    }
}

// ---------------- Sn build (+ P init fused) ----------------
// grid (256, BATCH), 256 threads
__global__ void sn_kernel() {
    int i = blockIdx.x, b = blockIdx.y, j = threadIdx.x;
    int src = (i < 128 && j >= 128) ? j * DIM + i : i * DIM + j;
    float v = 0.f;
#pragma unroll
    for (int s = 0; s < NSPLIT; s++)
        v += g_part[(size_t)(s * BATCH + b) * DIM * DIM + src];
    v *= g_trinv[b];
    size_t idx = (size_t)b * DIM * DIM + i * DIM + j;
    bf16 h = __float2bfloat16(v);
    g_Sn_hi[idx] = h;
    g_Sn_lo[idx] = __float2bfloat16(v - __bfloat162float(h));
    float pv = (i == j) ? 1.f : 0.f;
    g_Pf[idx] = pv;
    g_P_hi[idx] = __float2bfloat16(pv);
    g_P_lo[idx] = __float2bfloat16(0.f);
}

// ---------------- NS gemm body ----------------
__device__ __forceinline__ void ns_gemm_body(int aSel, int bSel, int dSel, int mode,
                                             int tm, int tn, int b, char* smem) {
    int tid = threadIdx.x, lane = tid & 31, wid = tid >> 5;
    int wm = wid & 1, wn = wid >> 1;
    size_t mb = (size_t)b * DIM * DIM;

    const bf16* Ah = selh(aSel) + mb + (size_t)tm * 64 * DIM;
    const bf16* Al = sell(aSel) + mb + (size_t)tm * 64 * DIM;
    const bf16* Bh = selh(bSel) + mb + (size_t)tn * 128 * DIM;
    const bf16* Bl = sell(bSel) + mb + (size_t)tn * 128 * DIM;

    float acc[CoreB::MT][CoreB::NG][4] = {};
    CoreB::run(Ah, Al, DIM, Bh, Bl, DIM, DIM, smem, acc, tid, wm, wn, lane);

    bf16* dh = selh_w(dSel) + mb;
    bf16* dl = sell_w(dSel) + mb;
    float* pf = g_Pf + mb;
#pragma unroll
    for (int mt = 0; mt < CoreB::MT; mt++) {
        int row = tm * 64 + wm * CoreB::WTM + mt * 16 + (lane >> 2);
#pragma unroll
        for (int g = 0; g < CoreB::NG; g++) {
            int col = tn * 128 + wn * CoreB::WTN + g * 8 + (lane & 3) * 2;
#pragma unroll
            for (int h = 0; h < 2; h++) {
                size_t idx = (size_t)(row + h * 8) * DIM + col;
                float v0 = acc[mt][g][2 * h], v1 = acc[mt][g][2 * h + 1];
                if (mode == 2) {
                    v0 = 1.5f * pf[idx] - 0.5f * v0;
                    v1 = 1.5f * pf[idx + 1] - 0.5f * v1;
                    pf[idx] = v0;
                    pf[idx + 1] = v1;
                }
                store_split2(dh, dl, idx, v0, v1);
            }
        }
    }
}

// pair launch: blockIdx.x 0..15 -> sub 0: T1 = P@P ; sub 1: T2 = P@Sn
// grid (16, BATCH), 256 threads
__global__ void __launch_bounds__(256) ns_pair_kernel() {
    extern __shared__ char smem[];
    int sub = blockIdx.x >> 3;
    int t = blockIdx.x & 7;
    int tm = t & 3, tn = t >> 2;
    if (sub == 0) ns_gemm_body(0, 0, 1, 0, tm, tn, blockIdx.y, smem);
    else          ns_gemm_body(0, 3, 2, 0, tm, tn, blockIdx.y, smem);
}

// final: P = 1.5P - 0.5*T1@T2^T
// grid (8, BATCH), 256 threads
__global__ void __launch_bounds__(256) ns_fin_kernel() {
    extern __shared__ char smem[];
    int tm = blockIdx.x & 3, tn = blockIdx.x >> 2;
    ns_gemm_body(1, 2, 0, 2, tm, tn, blockIdx.y, smem);
}

// ---------------- out = (xn @ P) * scale ----------------
// grid (2, SEQ/128, BATCH), 128 threads
__global__ void __launch_bounds__(128) out_mma_kernel(float* __restrict__ out) {
    extern __shared__ char smem[];
    int tid = threadIdx.x, lane = tid & 31, wid = tid >> 5;
    int wm = wid & 1, wn = wid >> 1;
    int tn = blockIdx.x;
    int s0 = blockIdx.y * 128;
    int b = blockIdx.z;

    const bf16* Ah = g_xn_hi + ((size_t)b * SEQ + s0) * DIM;
    const bf16* Al = g_xn_lo + ((size_t)b * SEQ + s0) * DIM;
    const bf16* Bh = g_P_hi + (size_t)b * DIM * DIM + (size_t)tn * 128 * DIM;
    const bf16* Bl = g_P_lo + (size_t)b * DIM * DIM + (size_t)tn * 128 * DIM;

    float acc[CoreA::MT][CoreA::NG][4] = {};
    CoreA::run(Ah, Al, DIM, Bh, Bl, DIM, DIM, smem, acc, tid, wm, wn, lane);

    float sc = g_scale[b];
    float* ob = out + ((size_t)b * SEQ + s0) * DIM + tn * 128;
#pragma unroll
    for (int mt = 0; mt < CoreA::MT; mt++) {
        int row = wm * CoreA::WTM + mt * 16 + (lane >> 2);
#pragma unroll
        for (int g = 0; g < CoreA::NG; g++) {
            int col = wn * CoreA::WTN + g * 8 + (lane & 3) * 2;
            *reinterpret_cast<float2*>(&ob[(size_t)row * DIM + col]) =
                make_float2(acc[mt][g][0] * sc, acc[mt][g][1] * sc);
            *reinterpret_cast<float2*>(&ob[(size_t)(row + 8) * DIM + col]) =
                make_float2(acc[mt][g][2] * sc, acc[mt][g][3] * sc);
        }
    }
}

// ---------------- launch ----------------
extern "C" void kernel_launch(void* const* d_in, const int* in_sizes, int n_in,
                              void* d_out, int out_size) {
    const float* x = (const float*)d_in[0];
    float* out = (float*)d_out;

    static bool attrs_set = false;
    if (!attrs_set) {
        cudaFuncSetAttribute(sigma_mma_kernel, cudaFuncAttributeMaxDynamicSharedMemorySize, 2 * SG_STAGE);
        cudaFuncSetAttribute(out_mma_kernel, cudaFuncAttributeMaxDynamicSharedMemorySize, 2 * CoreA::STAGE);
        cudaFuncSetAttribute(ns_pair_kernel, cudaFuncAttributeMaxDynamicSharedMemorySize, 2 * CoreB::STAGE);
        cudaFuncSetAttribute(ns_fin_kernel, cudaFuncAttributeMaxDynamicSharedMemorySize, 2 * CoreB::STAGE);
        attrs_set = true;
    }

    zero_mean_kernel<<<16, 256>>>();
    mean_kernel<<<dim3(SEQ / 128, BATCH), 256>>>(x);
    convert_kernel<<<dim3(SEQ / 32, BATCH), 256>>>(x);
    sigma_mma_kernel<<<dim3(3, NSPLIT, BATCH), 128, 2 * SG_STAGE>>>();
    trace_kernel<<<BATCH, 256>>>();
    sn_kernel<<<dim3(256, BATCH), 256>>>();

    for (int it = 0; it < 4; it++) {
        ns_pair_kernel<<<dim3(16, BATCH), 256, 2 * CoreB::STAGE>>>();  // T1=P@P, T2=P@Sn
        ns_fin_kernel<<<dim3(8, BATCH), 256, 2 * CoreB::STAGE>>>();    // P=1.5P-0.5*T1@T2^T
    }

    out_mma_kernel<<<dim3(2, SEQ / 128, BATCH), 128, 2 * CoreA::STAGE>>>(out);
}